// round 1
// baseline (speedup 1.0000x reference)
#include <cuda_runtime.h>
#include <math.h>

#define N_  8
#define C_  512
#define T_  4096
#define G_  32
#define CG_ 16      // C_/G_
#define EPS_ 1e-5f
#define OFFSET_ELEMS (N_*2*T_)   // 65536

// Scratch (device globals — no cudaMalloc allowed)
__device__ float g_h[(size_t)N_*C_*T_];        // conv1 output, then normalized+relu'd
__device__ float g_S[2][(size_t)N_*C_*T_];     // sampled planes for taps k=0 and k=2
__device__ float g_mean[N_*G_];
__device__ float g_rstd[N_*G_];

// ---------------------------------------------------------------------------
// conv1: g_h[n,o,t] = conv_b[o] + sum_{ci,k} W[o,ci,k] * feat[n,ci,t+k-1]
// Tiled SGEMM: 64 (o) x 64 (t) per block, KC=16, 4x4 per thread.
// ---------------------------------------------------------------------------
__global__ __launch_bounds__(256) void conv1_kernel(const float* __restrict__ x,
                                                    const float* __restrict__ W,
                                                    const float* __restrict__ b) {
    __shared__ float sW[64][48];   // [o][ci*3+k]
    __shared__ float sX[16][68];   // [ci][t0-1 .. t0+64] (66 used, padded)

    const int n  = blockIdx.z;
    const int o0 = blockIdx.y * 64;
    const int t0 = blockIdx.x * 64;
    const int tid = threadIdx.x;
    const int tx = tid & 15, ty = tid >> 4;

    float acc[4][4] = {};
    const float* xb = x + (size_t)n * C_ * T_;

    for (int c0 = 0; c0 < C_; c0 += 16) {
        // load W tile: 64 rows x 48 contiguous floats each (coalesced)
        #pragma unroll
        for (int l = tid; l < 64*48; l += 256) {
            int o = l / 48, r = l % 48;
            sW[o][r] = W[(size_t)(o0 + o) * (C_*3) + (size_t)c0 * 3 + r];
        }
        // load X tile: 16 x 66, index u -> time t0-1+u, zero-padded
        #pragma unroll
        for (int l = tid; l < 16*66; l += 256) {
            int ci = l / 66, u = l % 66;
            int t = t0 - 1 + u;
            float v = 0.0f;
            if (t >= 0 && t < T_) v = xb[(size_t)(c0 + ci) * T_ + t];
            sX[ci][u] = v;
        }
        __syncthreads();

        #pragma unroll
        for (int ci = 0; ci < 16; ci++) {
            float xv[6];
            #pragma unroll
            for (int u = 0; u < 6; u++) xv[u] = sX[ci][tx*4 + u];
            #pragma unroll
            for (int k = 0; k < 3; k++) {
                float w0 = sW[ty*4+0][ci*3+k];
                float w1 = sW[ty*4+1][ci*3+k];
                float w2 = sW[ty*4+2][ci*3+k];
                float w3 = sW[ty*4+3][ci*3+k];
                #pragma unroll
                for (int j = 0; j < 4; j++) {
                    float xj = xv[j + k];
                    acc[0][j] = fmaf(w0, xj, acc[0][j]);
                    acc[1][j] = fmaf(w1, xj, acc[1][j]);
                    acc[2][j] = fmaf(w2, xj, acc[2][j]);
                    acc[3][j] = fmaf(w3, xj, acc[3][j]);
                }
            }
        }
        __syncthreads();
    }

    #pragma unroll
    for (int oi = 0; oi < 4; oi++) {
        int o = o0 + ty*4 + oi;
        float bias = b[o];
        float* out = g_h + ((size_t)n * C_ + o) * T_ + t0 + tx*4;
        #pragma unroll
        for (int j = 0; j < 4; j++) out[j] = acc[oi][j] + bias;
    }
}

// ---------------------------------------------------------------------------
// GroupNorm stats: one block per (n, group); reduce sum/sumsq over 16*4096.
// ---------------------------------------------------------------------------
__global__ __launch_bounds__(256) void gn_stats_kernel() {
    const int n = blockIdx.x / G_;
    const int g = blockIdx.x % G_;
    const float* p = g_h + ((size_t)n * C_ + (size_t)g * CG_) * T_;
    const int M = CG_ * T_;

    float s = 0.f, ss = 0.f;
    for (int i = threadIdx.x; i < M; i += 256) {
        float v = p[i];
        s += v; ss += v * v;
    }
    __shared__ float rs[256], rq[256];
    rs[threadIdx.x] = s; rq[threadIdx.x] = ss;
    __syncthreads();
    for (int st = 128; st > 0; st >>= 1) {
        if (threadIdx.x < st) { rs[threadIdx.x] += rs[threadIdx.x+st]; rq[threadIdx.x] += rq[threadIdx.x+st]; }
        __syncthreads();
    }
    if (threadIdx.x == 0) {
        float m = rs[0] / (float)M;
        float var = rq[0] / (float)M - m * m;
        g_mean[blockIdx.x] = m;
        g_rstd[blockIdx.x] = rsqrtf(var + EPS_);
    }
}

// ---------------------------------------------------------------------------
// Normalize + affine + relu, in place on g_h.
// ---------------------------------------------------------------------------
__global__ __launch_bounds__(256) void gn_norm_kernel(const float* __restrict__ gamma,
                                                      const float* __restrict__ beta) {
    const size_t total = (size_t)N_ * C_ * T_;
    for (size_t idx = (size_t)blockIdx.x * blockDim.x + threadIdx.x; idx < total;
         idx += (size_t)gridDim.x * blockDim.x) {
        int c = (int)((idx / T_) % C_);
        int n = (int)(idx / ((size_t)C_ * T_));
        int gi = n * G_ + c / CG_;
        float v = (g_h[idx] - g_mean[gi]) * g_rstd[gi] * gamma[c] + beta[c];
        g_h[idx] = fmaxf(v, 0.0f);
    }
}

// ---------------------------------------------------------------------------
// Bilinear sampling for deform taps k=0 and k=2 (tap k=1 is identity).
// One thread per (n, tap, t); loops over 512 channels.
// ---------------------------------------------------------------------------
__global__ __launch_bounds__(256) void sample_kernel(const float* __restrict__ locs,
                                                     const int* __restrict__ stride_p) {
    int idx = blockIdx.x * blockDim.x + threadIdx.x;
    if (idx >= N_ * 2 * T_) return;
    int t  = idx % T_;
    int kk = (idx / T_) % 2;        // 0 -> tap k=0 (locs row 0), 1 -> tap k=2 (locs row 1)
    int n  = idx / (2 * T_);

    // robust stride read: int32 little-endian works for int32/int64; fall back to float bits
    int sv = *stride_p;
    float fs = (sv > 0 && sv < 1000000) ? (float)sv : __int_as_float(sv);

    float y = locs[((size_t)n * 2 + kk) * T_ + t] / fs;
    float pos = (kk == 0) ? ((float)t - 1.0f - y) : ((float)t + 1.0f + y);
    float p0 = floorf(pos);
    float w1 = pos - p0;
    int i0 = (int)p0;
    int i1 = i0 + 1;
    float wa = (1.0f - w1) * ((i0 >= 0 && i0 < T_) ? 1.0f : 0.0f);
    float wb = w1          * ((i1 >= 0 && i1 < T_) ? 1.0f : 0.0f);
    int i0c = min(max(i0, 0), T_ - 1);
    int i1c = min(max(i1, 0), T_ - 1);

    const float* hb = g_h + (size_t)n * C_ * T_;
    float* Sb = g_S[kk] + (size_t)n * C_ * T_ + t;
    for (int ci = 0; ci < C_; ci++) {
        const float* hr = hb + (size_t)ci * T_;
        Sb[(size_t)ci * T_] = wa * hr[i0c] + wb * hr[i1c];
    }
}

// ---------------------------------------------------------------------------
// Deform conv as SGEMM over 3 tap planes: out = relu(sum_k W_k @ S_k + b)
// S_0 = g_S[0], S_1 = g_h, S_2 = g_S[1]. Writes offset_feat region of d_out.
// ---------------------------------------------------------------------------
__global__ __launch_bounds__(256) void dconv_kernel(const float* __restrict__ W,
                                                    const float* __restrict__ b,
                                                    float* __restrict__ out_feat) {
    __shared__ float sW[64][48];       // [o][ci*3+k]
    __shared__ float sS[3][16][64];    // [k][ci][t]

    const int n  = blockIdx.z;
    const int o0 = blockIdx.y * 64;
    const int t0 = blockIdx.x * 64;
    const int tid = threadIdx.x;
    const int tx = tid & 15, ty = tid >> 4;

    float acc[4][4] = {};

    for (int c0 = 0; c0 < C_; c0 += 16) {
        #pragma unroll
        for (int l = tid; l < 64*48; l += 256) {
            int o = l / 48, r = l % 48;
            sW[o][r] = W[(size_t)(o0 + o) * (C_*3) + (size_t)c0 * 3 + r];
        }
        #pragma unroll
        for (int l = tid; l < 16*64; l += 256) {
            int ci = l >> 6, u = l & 63;
            size_t off = ((size_t)n * C_ + c0 + ci) * T_ + t0 + u;
            sS[0][ci][u] = g_S[0][off];
            sS[1][ci][u] = g_h[off];
            sS[2][ci][u] = g_S[1][off];
        }
        __syncthreads();

        #pragma unroll
        for (int ci = 0; ci < 16; ci++) {
            #pragma unroll
            for (int k = 0; k < 3; k++) {
                float w0 = sW[ty*4+0][ci*3+k];
                float w1 = sW[ty*4+1][ci*3+k];
                float w2 = sW[ty*4+2][ci*3+k];
                float w3 = sW[ty*4+3][ci*3+k];
                #pragma unroll
                for (int j = 0; j < 4; j++) {
                    float xj = sS[k][ci][tx*4 + j];
                    acc[0][j] = fmaf(w0, xj, acc[0][j]);
                    acc[1][j] = fmaf(w1, xj, acc[1][j]);
                    acc[2][j] = fmaf(w2, xj, acc[2][j]);
                    acc[3][j] = fmaf(w3, xj, acc[3][j]);
                }
            }
        }
        __syncthreads();
    }

    #pragma unroll
    for (int oi = 0; oi < 4; oi++) {
        int o = o0 + ty*4 + oi;
        float bias = b[o];
        float* out = out_feat + ((size_t)n * C_ + o) * T_ + t0 + tx*4;
        #pragma unroll
        for (int j = 0; j < 4; j++) out[j] = fmaxf(acc[oi][j] + bias, 0.0f);
    }
}

// ---------------------------------------------------------------------------
// Final conv: offset[n,o,t] = out_b[o] + sum_{i,k} out_w[o,i,k]*feat[n,i,t+k-1]
// O=2; weights cached in smem; one thread per (n,t).
// ---------------------------------------------------------------------------
__global__ __launch_bounds__(256) void outconv_kernel(const float* __restrict__ W,
                                                      const float* __restrict__ b,
                                                      const float* __restrict__ feat,
                                                      float* __restrict__ out) {
    __shared__ float sW[2 * C_ * 3];
    for (int l = threadIdx.x; l < 2 * C_ * 3; l += 256) sW[l] = W[l];
    __syncthreads();

    int idx = blockIdx.x * blockDim.x + threadIdx.x;   // over N*T
    int t = idx % T_;
    int n = idx / T_;
    const float* fb = feat + (size_t)n * C_ * T_;
    float a0 = b[0], a1 = b[1];
    bool lok = (t >= 1), rok = (t < T_ - 1);
    for (int i = 0; i < C_; i++) {
        const float* fr = fb + (size_t)i * T_ + t;
        float vm = lok ? fr[-1] : 0.0f;
        float v0 = fr[0];
        float vp = rok ? fr[1] : 0.0f;
        a0 = fmaf(sW[i*3+0], vm, a0);
        a0 = fmaf(sW[i*3+1], v0, a0);
        a0 = fmaf(sW[i*3+2], vp, a0);
        a1 = fmaf(sW[(C_+i)*3+0], vm, a1);
        a1 = fmaf(sW[(C_+i)*3+1], v0, a1);
        a1 = fmaf(sW[(C_+i)*3+2], vp, a1);
    }
    out[(size_t)n * 2 * T_ + t]       = a0;
    out[((size_t)n * 2 + 1) * T_ + t] = a1;
}

// ---------------------------------------------------------------------------
extern "C" void kernel_launch(void* const* d_in, const int* in_sizes, int n_in,
                              void* d_out, int out_size) {
    const float* feat   = (const float*)d_in[0];
    const float* locs   = (const float*)d_in[1];
    const float* conv_w = (const float*)d_in[2];
    const float* conv_b = (const float*)d_in[3];
    const float* gn_g   = (const float*)d_in[4];
    const float* gn_b   = (const float*)d_in[5];
    const float* dcn_w  = (const float*)d_in[6];
    const float* dcn_b  = (const float*)d_in[7];
    const float* out_w  = (const float*)d_in[8];
    const float* out_b  = (const float*)d_in[9];
    const int*   stride = (const int*)d_in[10];

    float* out        = (float*)d_out;                 // offset: N*2*T floats
    float* out_feat   = (float*)d_out + OFFSET_ELEMS;  // offset_feat: N*C*T floats

    dim3 gemm_grid(T_/64, C_/64, N_);   // 64 x 8 x 8

    conv1_kernel<<<gemm_grid, 256>>>(feat, conv_w, conv_b);
    gn_stats_kernel<<<N_*G_, 256>>>();
    gn_norm_kernel<<<16384, 256>>>(gn_g, gn_b);
    sample_kernel<<<(N_*2*T_ + 255)/256, 256>>>(locs, stride);
    dconv_kernel<<<gemm_grid, 256>>>(dcn_w, dcn_b, out_feat);
    outconv_kernel<<<(N_*T_ + 255)/256, 256>>>(out_w, out_b, out_feat, out);
}

// round 4
// speedup vs baseline: 2.7158x; 2.7158x over previous
#include <cuda_runtime.h>
#include <cuda_bf16.h>
#include <cstdint>
#include <math.h>

#define N_  8
#define C_  512
#define T_  4096
#define TPAD (T_+2)
#define G_  32
#define EPS_ 1e-5f
#define OFFSET_ELEMS (N_*2*T_)

#define TMT 128
#define TNT 128
#define KC  64
#define NCHUNK 24   // 3 taps * (512/64)

// ---------------- device scratch ----------------
__device__ float g_h[(size_t)N_*C_*T_];          // conv1 raw [n][c][t]
__device__ float g_hnT[(size_t)N_*T_*C_];        // normalized+relu fp32 [n][t][c]
__device__ float g_mean[N_*G_], g_rstd[N_*G_];
// weights: [conv][tap][o][ci] bf16 hi/lo
__device__ __nv_bfloat16 g_Wh[2][3*C_*C_];
__device__ __nv_bfloat16 g_Wl[2][3*C_*C_];
// T-major activation planes, padded rows [n][TPAD][C] (row 0 and TPAD-1 are guards)
__device__ __nv_bfloat16 g_xTh[(size_t)N_*TPAD*C_], g_xTl[(size_t)N_*TPAD*C_];
__device__ __nv_bfloat16 g_hTh[(size_t)N_*TPAD*C_], g_hTl[(size_t)N_*TPAD*C_];
__device__ __nv_bfloat16 g_S0h[(size_t)N_*TPAD*C_], g_S0l[(size_t)N_*TPAD*C_];
__device__ __nv_bfloat16 g_S2h[(size_t)N_*TPAD*C_], g_S2l[(size_t)N_*TPAD*C_];

// ---------------- PTX helpers ----------------
__device__ __forceinline__ uint32_t smem_u32(const void* p) {
    uint32_t a;
    asm("{ .reg .u64 t; cvta.to.shared.u64 t, %1; cvt.u32.u64 %0, t; }" : "=r"(a) : "l"(p));
    return a;
}
__device__ __forceinline__ void cp_async16(uint32_t saddr, const void* gaddr) {
    asm volatile("cp.async.cg.shared.global [%0], [%1], 16;" :: "r"(saddr), "l"(gaddr));
}
__device__ __forceinline__ void ldsm4(uint32_t* r, uint32_t addr) {
    asm volatile("ldmatrix.sync.aligned.m8n8.x4.shared.b16 {%0,%1,%2,%3}, [%4];"
        : "=r"(r[0]), "=r"(r[1]), "=r"(r[2]), "=r"(r[3]) : "r"(addr));
}
__device__ __forceinline__ void mma16816(float* d, const uint32_t* a, uint32_t b0, uint32_t b1) {
    asm volatile("mma.sync.aligned.m16n8k16.row.col.f32.bf16.bf16.f32 "
        "{%0,%1,%2,%3}, {%4,%5,%6,%7}, {%8,%9}, {%0,%1,%2,%3};"
        : "+f"(d[0]), "+f"(d[1]), "+f"(d[2]), "+f"(d[3])
        : "r"(a[0]), "r"(a[1]), "r"(a[2]), "r"(a[3]), "r"(b0), "r"(b1));
}

// ---------------- prep: weights -> bf16 hi/lo, [tap][o][ci] ----------------
__global__ __launch_bounds__(256) void prep_w_kernel(const float* __restrict__ w1,
                                                     const float* __restrict__ w2) {
    const int conv = blockIdx.y;
    const float* w = conv ? w2 : w1;
    __nv_bfloat16* Wh = g_Wh[conv];
    __nv_bfloat16* Wl = g_Wl[conv];
    const int total = 3 * C_ * C_;
    for (int idx = blockIdx.x * 256 + threadIdx.x; idx < total; idx += gridDim.x * 256) {
        int k = idx / (C_ * C_);
        int rem = idx % (C_ * C_);
        int o = rem / C_, ci = rem % C_;
        float v = w[((size_t)o * C_ + ci) * 3 + k];
        __nv_bfloat16 h = __float2bfloat16_rn(v);
        Wh[idx] = h;
        Wl[idx] = __float2bfloat16_rn(v - __bfloat162float(h));
    }
}

// ---------------- prep: feat [n][c][t] -> xT hi/lo [n][1+t][c]; zero guards ----------------
__global__ __launch_bounds__(256) void prep_x_kernel(const float* __restrict__ feat) {
    __shared__ float sx[64][65];
    int n = blockIdx.z, c0 = blockIdx.y * 64, t0 = blockIdx.x * 64;
    const float* xb = feat + ((size_t)n * C_ + c0) * T_ + t0;
    for (int i = threadIdx.x; i < 64 * 64; i += 256) {
        int ci = i >> 6, t = i & 63;
        sx[ci][t] = xb[(size_t)ci * T_ + t];
    }
    __syncthreads();
    for (int i = threadIdx.x; i < 64 * 64; i += 256) {
        int ci = i & 63, t = i >> 6;
        float v = sx[ci][t];
        size_t dst = ((size_t)n * TPAD + 1 + t0 + t) * C_ + c0 + ci;
        __nv_bfloat16 h = __float2bfloat16_rn(v);
        g_xTh[dst] = h;
        g_xTl[dst] = __float2bfloat16_rn(v - __bfloat162float(h));
    }
}

__global__ __launch_bounds__(256) void zero_guard_kernel() {
    // zero guard rows (0 and TPAD-1) of xT planes
    int idx = blockIdx.x * 256 + threadIdx.x;      // over N_*C_
    if (idx >= N_ * C_) return;
    int n = idx / C_, ci = idx % C_;
    size_t r0 = ((size_t)n * TPAD) * C_ + ci;
    size_t r1 = ((size_t)n * TPAD + TPAD - 1) * C_ + ci;
    __nv_bfloat16 z = __float2bfloat16_rn(0.f);
    g_xTh[r0] = z; g_xTh[r1] = z;
    g_xTl[r0] = z; g_xTl[r1] = z;
}

// ---------------- bf16 MMA GEMM ----------------
// out[n][o][t] = bias[o] + sum_tap sum_ci W[tap][o][ci] * Btap[n][1+t+roff_tap][ci]
extern __shared__ char smem_raw[];
__global__ __launch_bounds__(256, 1) void gemm_kernel(
    const __nv_bfloat16* __restrict__ Wh, const __nv_bfloat16* __restrict__ Wl,
    const __nv_bfloat16* __restrict__ B0h, const __nv_bfloat16* __restrict__ B0l,
    const __nv_bfloat16* __restrict__ B1h, const __nv_bfloat16* __restrict__ B1l,
    const __nv_bfloat16* __restrict__ B2h, const __nv_bfloat16* __restrict__ B2l,
    int r0off, int r1off, int r2off,
    const float* __restrict__ bias, float* __restrict__ out, int relu)
{
    const int tid = threadIdx.x, lane = tid & 31, wid = tid >> 5;
    const int nB = blockIdx.z, o0 = blockIdx.y * TMT, t0 = blockIdx.x * TNT;

    const uint32_t sb = smem_u32(smem_raw);
    // stage layout: stage*65536 + {Ah:0, Al:16384, Bh:32768, Bl:49152}

    // per-warp tile coords
    const int m0 = (wid >> 2) * 64;
    const int nw = (wid & 3) * 32;
    const int arow = lane & 15, acb = lane >> 4;
    const int brow = (lane & 7) + ((lane >> 4) << 3), bcb = (lane >> 3) & 1;
    uint32_t aoff[4], a7[4], boff[2], b7[2];
    #pragma unroll
    for (int mf = 0; mf < 4; mf++) {
        int r = m0 + mf * 16 + arow;
        aoff[mf] = (uint32_t)(r * 128); a7[mf] = (uint32_t)(r & 7);
    }
    #pragma unroll
    for (int p = 0; p < 2; p++) {
        int r = nw + p * 16 + brow;
        boff[p] = (uint32_t)(r * 128); b7[p] = (uint32_t)(r & 7);
    }

    float acc[4][4][4];
    #pragma unroll
    for (int a = 0; a < 4; a++)
        #pragma unroll
        for (int b = 0; b < 4; b++)
            #pragma unroll
            for (int c = 0; c < 4; c++) acc[a][b][c] = 0.f;

    auto load_chunk = [&](int c, int s) {
        const int tap = c >> 3, ci0 = (c & 7) * 64;
        const __nv_bfloat16 *bh, *bl; int ro;
        if (tap == 0)      { bh = B0h; bl = B0l; ro = r0off; }
        else if (tap == 1) { bh = B1h; bl = B1l; ro = r1off; }
        else               { bh = B2h; bl = B2l; ro = r2off; }
        const size_t brow0 = (size_t)nB * TPAD + 1 + t0 + ro;
        const __nv_bfloat16* wh = Wh + ((size_t)tap * C_ + o0) * C_ + ci0;
        const __nv_bfloat16* wl = Wl + ((size_t)tap * C_ + o0) * C_ + ci0;
        const uint32_t st = sb + (uint32_t)s * 65536u;
        #pragma unroll
        for (int it = 0; it < 4; it++) {
            int i = tid + it * 256;          // 0..1023 = 128 rows x 8 chunks
            int row = i >> 3, q = i & 7;
            uint32_t so = (uint32_t)(row * 128 + ((q ^ (row & 7)) << 4));
            cp_async16(st + so,          wh + (size_t)row * C_ + q * 8);
            cp_async16(st + 16384u + so, wl + (size_t)row * C_ + q * 8);
            const size_t bo = (brow0 + row) * C_ + ci0 + q * 8;
            cp_async16(st + 32768u + so, bh + bo);
            cp_async16(st + 49152u + so, bl + bo);
        }
        asm volatile("cp.async.commit_group;" ::: "memory");
    };

    auto compute = [&](int s) {
        const uint32_t Ab  = sb + (uint32_t)s * 65536u;
        const uint32_t Alb = Ab + 16384u;
        const uint32_t Bb  = Ab + 32768u;
        const uint32_t Blb = Ab + 49152u;
        #pragma unroll
        for (int ks = 0; ks < 4; ks++) {
            uint32_t ah[4][4], al[4][4], bhv[2][4], blv[2][4];
            #pragma unroll
            for (int mf = 0; mf < 4; mf++) {
                uint32_t off = aoff[mf] + ((((uint32_t)(2*ks) + acb) ^ a7[mf]) << 4);
                ldsm4(ah[mf], Ab + off);
                ldsm4(al[mf], Alb + off);
            }
            #pragma unroll
            for (int p = 0; p < 2; p++) {
                uint32_t off = boff[p] + ((((uint32_t)(2*ks) + bcb) ^ b7[p]) << 4);
                ldsm4(bhv[p], Bb + off);
                ldsm4(blv[p], Blb + off);
            }
            #pragma unroll
            for (int mf = 0; mf < 4; mf++) {
                #pragma unroll
                for (int nf = 0; nf < 4; nf++) {
                    int p = nf >> 1, j = (nf & 1) * 2;
                    mma16816(acc[mf][nf], ah[mf], bhv[p][j], bhv[p][j+1]);
                    mma16816(acc[mf][nf], ah[mf], blv[p][j], blv[p][j+1]);
                    mma16816(acc[mf][nf], al[mf], bhv[p][j], bhv[p][j+1]);
                }
            }
        }
    };

    load_chunk(0, 0);
    load_chunk(1, 1);
    for (int c = 0; c < NCHUNK; c++) {
        if (c == NCHUNK - 1) asm volatile("cp.async.wait_group 0;" ::: "memory");
        else                 asm volatile("cp.async.wait_group 1;" ::: "memory");
        __syncthreads();
        compute(c & 1);
        __syncthreads();
        if (c + 2 < NCHUNK) load_chunk(c + 2, c & 1);   // FIX: (chunk, stage) order
    }

    // epilogue
    #pragma unroll
    for (int mf = 0; mf < 4; mf++) {
        int rowA = o0 + m0 + mf * 16 + (lane >> 2);
        int rowB = rowA + 8;
        float bA = bias[rowA], bB = bias[rowB];
        float* pA = out + ((size_t)nB * C_ + rowA) * T_ + t0;
        float* pB = out + ((size_t)nB * C_ + rowB) * T_ + t0;
        #pragma unroll
        for (int nf = 0; nf < 4; nf++) {
            int col = nw + nf * 8 + (lane & 3) * 2;
            float2 vA = make_float2(acc[mf][nf][0] + bA, acc[mf][nf][1] + bA);
            float2 vB = make_float2(acc[mf][nf][2] + bB, acc[mf][nf][3] + bB);
            if (relu) {
                vA.x = fmaxf(vA.x, 0.f); vA.y = fmaxf(vA.y, 0.f);
                vB.x = fmaxf(vB.x, 0.f); vB.y = fmaxf(vB.y, 0.f);
            }
            *reinterpret_cast<float2*>(pA + col) = vA;
            *reinterpret_cast<float2*>(pB + col) = vB;
        }
    }
}

// ---------------- GroupNorm stats ----------------
__global__ __launch_bounds__(256) void gn_stats_kernel() {
    const int n = blockIdx.x / G_;
    const int g = blockIdx.x % G_;
    const float* p = g_h + ((size_t)n * C_ + (size_t)g * 16) * T_;
    const int M = 16 * T_;
    float s = 0.f, ss = 0.f;
    for (int i = threadIdx.x; i < M; i += 256) { float v = p[i]; s += v; ss += v * v; }
    __shared__ float rs[256], rq[256];
    rs[threadIdx.x] = s; rq[threadIdx.x] = ss;
    __syncthreads();
    for (int st = 128; st > 0; st >>= 1) {
        if (threadIdx.x < st) { rs[threadIdx.x] += rs[threadIdx.x+st]; rq[threadIdx.x] += rq[threadIdx.x+st]; }
        __syncthreads();
    }
    if (threadIdx.x == 0) {
        float m = rs[0] / (float)M;
        float var = rq[0] / (float)M - m * m;
        g_mean[blockIdx.x] = m;
        g_rstd[blockIdx.x] = rsqrtf(var + EPS_);
    }
}

// ---------------- normalize+relu -> hnT fp32 + hT hi/lo planes ----------------
__global__ __launch_bounds__(256) void norm_t_kernel(const float* __restrict__ gamma,
                                                     const float* __restrict__ beta) {
    __shared__ float st[64][65];
    int n = blockIdx.z, c0 = blockIdx.y * 64, t0 = blockIdx.x * 64;
    for (int i = threadIdx.x; i < 64 * 64; i += 256) {
        int ci = i >> 6, t = i & 63;
        int c = c0 + ci;
        float v = g_h[((size_t)n * C_ + c) * T_ + t0 + t];
        int gi = n * G_ + (c >> 4);
        v = fmaxf((v - g_mean[gi]) * g_rstd[gi] * gamma[c] + beta[c], 0.f);
        st[ci][t] = v;
    }
    __syncthreads();
    for (int i = threadIdx.x; i < 64 * 64; i += 256) {
        int ci = i & 63, t = i >> 6;
        float v = st[ci][t];
        g_hnT[((size_t)n * T_ + t0 + t) * C_ + c0 + ci] = v;
        size_t dst = ((size_t)n * TPAD + 1 + t0 + t) * C_ + c0 + ci;
        __nv_bfloat16 h = __float2bfloat16_rn(v);
        g_hTh[dst] = h;
        g_hTl[dst] = __float2bfloat16_rn(v - __bfloat162float(h));
    }
}

// ---------------- bilinear sampling -> S0/S2 hi/lo planes ----------------
__global__ __launch_bounds__(256) void sample_kernel(const float* __restrict__ locs,
                                                     const int* __restrict__ stride_p) {
    const int n = blockIdx.y;
    int sv = *stride_p;
    float fs = (sv > 0 && sv < 1000000) ? (float)sv : __int_as_float(sv);

    for (int tt = 0; tt < 16; tt++) {
        int t = blockIdx.x * 16 + tt;
        float y1 = locs[((size_t)n * 2 + 0) * T_ + t] / fs;
        float y2 = locs[((size_t)n * 2 + 1) * T_ + t] / fs;

        float pos0 = (float)t - 1.0f - y1;
        float f0 = floorf(pos0);
        float wb0 = pos0 - f0;
        int i00 = (int)f0, i01 = i00 + 1;
        bool ok00 = (i00 >= 0 && i00 < T_), ok01 = (i01 >= 0 && i01 < T_);
        const float* r00 = g_hnT + ((size_t)n * T_ + min(max(i00, 0), T_ - 1)) * C_;
        const float* r01 = g_hnT + ((size_t)n * T_ + min(max(i01, 0), T_ - 1)) * C_;

        float pos2 = (float)t + 1.0f + y2;
        float f2 = floorf(pos2);
        float wb2 = pos2 - f2;
        int i20 = (int)f2, i21 = i20 + 1;
        bool ok20 = (i20 >= 0 && i20 < T_), ok21 = (i21 >= 0 && i21 < T_);
        const float* r20 = g_hnT + ((size_t)n * T_ + min(max(i20, 0), T_ - 1)) * C_;
        const float* r21 = g_hnT + ((size_t)n * T_ + min(max(i21, 0), T_ - 1)) * C_;

        size_t dst = ((size_t)n * TPAD + 1 + t) * C_;
        for (int ci = threadIdx.x; ci < C_; ci += 256) {
            float a0 = ok00 ? r00[ci] : 0.f;
            float b0 = ok01 ? r01[ci] : 0.f;
            float s0 = a0 * (1.f - wb0) + b0 * wb0;
            __nv_bfloat16 h0 = __float2bfloat16_rn(s0);
            g_S0h[dst + ci] = h0;
            g_S0l[dst + ci] = __float2bfloat16_rn(s0 - __bfloat162float(h0));

            float a2 = ok20 ? r20[ci] : 0.f;
            float b2 = ok21 ? r21[ci] : 0.f;
            float s2 = a2 * (1.f - wb2) + b2 * wb2;
            __nv_bfloat16 h2 = __float2bfloat16_rn(s2);
            g_S2h[dst + ci] = h2;
            g_S2l[dst + ci] = __float2bfloat16_rn(s2 - __bfloat162float(h2));
        }
    }
}

// ---------------- final 512->2 conv ----------------
__global__ __launch_bounds__(256) void outconv_kernel(const float* __restrict__ W,
                                                      const float* __restrict__ b,
                                                      const float* __restrict__ feat,
                                                      float* __restrict__ out) {
    __shared__ float sW[2 * C_ * 3];
    for (int l = threadIdx.x; l < 2 * C_ * 3; l += 256) sW[l] = W[l];
    __syncthreads();

    int idx = blockIdx.x * blockDim.x + threadIdx.x;
    int t = idx % T_;
    int n = idx / T_;
    const float* fb = feat + (size_t)n * C_ * T_;
    float a0 = b[0], a1 = b[1];
    bool lok = (t >= 1), rok = (t < T_ - 1);
    for (int i = 0; i < C_; i++) {
        const float* fr = fb + (size_t)i * T_ + t;
        float vm = lok ? fr[-1] : 0.0f;
        float v0 = fr[0];
        float vp = rok ? fr[1] : 0.0f;
        a0 = fmaf(sW[i*3+0], vm, a0);
        a0 = fmaf(sW[i*3+1], v0, a0);
        a0 = fmaf(sW[i*3+2], vp, a0);
        a1 = fmaf(sW[(C_+i)*3+0], vm, a1);
        a1 = fmaf(sW[(C_+i)*3+1], v0, a1);
        a1 = fmaf(sW[(C_+i)*3+2], vp, a1);
    }
    out[(size_t)n * 2 * T_ + t]       = a0;
    out[((size_t)n * 2 + 1) * T_ + t] = a1;
}

// ---------------------------------------------------------------------------
extern "C" void kernel_launch(void* const* d_in, const int* in_sizes, int n_in,
                              void* d_out, int out_size) {
    const float* feat   = (const float*)d_in[0];
    const float* locs   = (const float*)d_in[1];
    const float* conv_w = (const float*)d_in[2];
    const float* conv_b = (const float*)d_in[3];
    const float* gn_g   = (const float*)d_in[4];
    const float* gn_b   = (const float*)d_in[5];
    const float* dcn_w  = (const float*)d_in[6];
    const float* dcn_b  = (const float*)d_in[7];
    const float* out_w  = (const float*)d_in[8];
    const float* out_b  = (const float*)d_in[9];
    const int*   stride = (const int*)d_in[10];

    float* out      = (float*)d_out;
    float* out_feat = (float*)d_out + OFFSET_ELEMS;

    __nv_bfloat16 *w1h, *w1l, *w2h, *w2l;
    __nv_bfloat16 *xth, *xtl, *hth, *htl, *s0h, *s0l, *s2h, *s2l;
    float *hbuf;
    cudaGetSymbolAddress((void**)&w1h, g_Wh);  w2h = w1h + 3*C_*C_;
    cudaGetSymbolAddress((void**)&w1l, g_Wl);  w2l = w1l + 3*C_*C_;
    cudaGetSymbolAddress((void**)&xth, g_xTh);
    cudaGetSymbolAddress((void**)&xtl, g_xTl);
    cudaGetSymbolAddress((void**)&hth, g_hTh);
    cudaGetSymbolAddress((void**)&htl, g_hTl);
    cudaGetSymbolAddress((void**)&s0h, g_S0h);
    cudaGetSymbolAddress((void**)&s0l, g_S0l);
    cudaGetSymbolAddress((void**)&s2h, g_S2h);
    cudaGetSymbolAddress((void**)&s2l, g_S2l);
    cudaGetSymbolAddress((void**)&hbuf, g_h);

    const int SMEM_BYTES = 2 * 65536;
    cudaFuncSetAttribute(gemm_kernel, cudaFuncAttributeMaxDynamicSharedMemorySize, SMEM_BYTES);

    dim3 tr_grid(T_/64, C_/64, N_);
    dim3 gemm_grid(T_/TNT, C_/TMT, N_);   // (32, 4, 8)

    prep_w_kernel<<<dim3(512, 2), 256>>>(conv_w, dcn_w);
    prep_x_kernel<<<tr_grid, 256>>>(feat);
    zero_guard_kernel<<<(N_*C_ + 255)/256, 256>>>();
    gemm_kernel<<<gemm_grid, 256, SMEM_BYTES>>>(w1h, w1l,
        xth, xtl, xth, xtl, xth, xtl, -1, 0, 1, conv_b, hbuf, 0);
    gn_stats_kernel<<<N_*G_, 256>>>();
    norm_t_kernel<<<tr_grid, 256>>>(gn_g, gn_b);
    sample_kernel<<<dim3(T_/16, N_), 256>>>(locs, stride);
    gemm_kernel<<<gemm_grid, 256, SMEM_BYTES>>>(w2h, w2l,
        s0h, s0l, hth, htl, s2h, s2l, 0, 0, 0, dcn_b, out_feat, 1);
    outconv_kernel<<<(N_*T_ + 255)/256, 256>>>(out_w, out_b, out_feat, out);
}

// round 5
// speedup vs baseline: 2.7765x; 1.0224x over previous
#include <cuda_runtime.h>
#include <cuda_bf16.h>
#include <cstdint>
#include <math.h>

#define N_  8
#define C_  512
#define T_  4096
#define TPAD (T_+2)
#define G_  32
#define EPS_ 1e-5f
#define OFFSET_ELEMS (N_*2*T_)

#define TMT 128
#define TNT 128
#define NCHUNK 24   // 3 taps * (512/64)
#define STAGES 3
#define STAGE_BYTES 65536

// ---------------- device scratch ----------------
__device__ float g_h[(size_t)N_*C_*T_];          // conv1 raw [n][c][t]
__device__ float g_mean[N_*G_], g_rstd[N_*G_];
__device__ float g_psum[N_][G_][32], g_psumsq[N_][G_][32];   // per-(n,g,tblock) partials
// weights: [conv][tap][o][ci] bf16 hi/lo
__device__ __nv_bfloat16 g_Wh[2][3*C_*C_];
__device__ __nv_bfloat16 g_Wl[2][3*C_*C_];
// T-major activation planes, padded rows [n][TPAD][C] (rows 0 and TPAD-1 are guards)
__device__ __nv_bfloat16 g_xTh[(size_t)N_*TPAD*C_], g_xTl[(size_t)N_*TPAD*C_];
__device__ __nv_bfloat16 g_hTh[(size_t)N_*TPAD*C_], g_hTl[(size_t)N_*TPAD*C_];
__device__ __nv_bfloat16 g_S0h[(size_t)N_*TPAD*C_], g_S0l[(size_t)N_*TPAD*C_];
__device__ __nv_bfloat16 g_S2h[(size_t)N_*TPAD*C_], g_S2l[(size_t)N_*TPAD*C_];

// ---------------- PTX helpers ----------------
__device__ __forceinline__ uint32_t smem_u32(const void* p) {
    uint32_t a;
    asm("{ .reg .u64 t; cvta.to.shared.u64 t, %1; cvt.u32.u64 %0, t; }" : "=r"(a) : "l"(p));
    return a;
}
__device__ __forceinline__ void cp_async16(uint32_t saddr, const void* gaddr) {
    asm volatile("cp.async.cg.shared.global [%0], [%1], 16;" :: "r"(saddr), "l"(gaddr));
}
__device__ __forceinline__ void ldsm4(uint32_t* r, uint32_t addr) {
    asm volatile("ldmatrix.sync.aligned.m8n8.x4.shared.b16 {%0,%1,%2,%3}, [%4];"
        : "=r"(r[0]), "=r"(r[1]), "=r"(r[2]), "=r"(r[3]) : "r"(addr));
}
__device__ __forceinline__ void mma16816(float* d, const uint32_t* a, uint32_t b0, uint32_t b1) {
    asm volatile("mma.sync.aligned.m16n8k16.row.col.f32.bf16.bf16.f32 "
        "{%0,%1,%2,%3}, {%4,%5,%6,%7}, {%8,%9}, {%0,%1,%2,%3};"
        : "+f"(d[0]), "+f"(d[1]), "+f"(d[2]), "+f"(d[3])
        : "r"(a[0]), "r"(a[1]), "r"(a[2]), "r"(a[3]), "r"(b0), "r"(b1));
}

// ---------------- prep: weights -> bf16 hi/lo, [tap][o][ci] ----------------
__global__ __launch_bounds__(256) void prep_w_kernel(const float* __restrict__ w1,
                                                     const float* __restrict__ w2) {
    const int conv = blockIdx.y;
    const float* w = conv ? w2 : w1;
    __nv_bfloat16* Wh = g_Wh[conv];
    __nv_bfloat16* Wl = g_Wl[conv];
    const int total = 3 * C_ * C_;
    for (int idx = blockIdx.x * 256 + threadIdx.x; idx < total; idx += gridDim.x * 256) {
        int k = idx / (C_ * C_);
        int rem = idx % (C_ * C_);
        int o = rem / C_, ci = rem % C_;
        float v = w[((size_t)o * C_ + ci) * 3 + k];
        __nv_bfloat16 h = __float2bfloat16_rn(v);
        Wh[idx] = h;
        Wl[idx] = __float2bfloat16_rn(v - __bfloat162float(h));
    }
}

// ---------------- prep: feat [n][c][t] -> xT hi/lo [n][1+t][c] ----------------
__global__ __launch_bounds__(256) void prep_x_kernel(const float* __restrict__ feat) {
    __shared__ float sx[64][65];
    int n = blockIdx.z, c0 = blockIdx.y * 64, t0 = blockIdx.x * 64;
    const float* xb = feat + ((size_t)n * C_ + c0) * T_ + t0;
    for (int i = threadIdx.x; i < 64 * 64; i += 256) {
        int ci = i >> 6, t = i & 63;
        sx[ci][t] = xb[(size_t)ci * T_ + t];
    }
    __syncthreads();
    for (int i = threadIdx.x; i < 64 * 64; i += 256) {
        int ci = i & 63, t = i >> 6;
        float v = sx[ci][t];
        size_t dst = ((size_t)n * TPAD + 1 + t0 + t) * C_ + c0 + ci;
        __nv_bfloat16 h = __float2bfloat16_rn(v);
        g_xTh[dst] = h;
        g_xTl[dst] = __float2bfloat16_rn(v - __bfloat162float(h));
    }
}

__global__ __launch_bounds__(256) void zero_guard_kernel() {
    int idx = blockIdx.x * 256 + threadIdx.x;      // over N_*C_
    if (idx >= N_ * C_) return;
    int n = idx / C_, ci = idx % C_;
    size_t r0 = ((size_t)n * TPAD) * C_ + ci;
    size_t r1 = ((size_t)n * TPAD + TPAD - 1) * C_ + ci;
    __nv_bfloat16 z = __float2bfloat16_rn(0.f);
    g_xTh[r0] = z; g_xTh[r1] = z;
    g_xTl[r0] = z; g_xTl[r1] = z;
}

// ---------------- bf16 MMA GEMM (3-stage cp.async pipeline) ----------------
extern __shared__ char smem_raw[];
__global__ __launch_bounds__(256, 1) void gemm_kernel(
    const __nv_bfloat16* __restrict__ Wh, const __nv_bfloat16* __restrict__ Wl,
    const __nv_bfloat16* __restrict__ B0h, const __nv_bfloat16* __restrict__ B0l,
    const __nv_bfloat16* __restrict__ B1h, const __nv_bfloat16* __restrict__ B1l,
    const __nv_bfloat16* __restrict__ B2h, const __nv_bfloat16* __restrict__ B2l,
    int r0off, int r1off, int r2off,
    const float* __restrict__ bias, float* __restrict__ out, int relu, int stats)
{
    const int tid = threadIdx.x, lane = tid & 31, wid = tid >> 5;
    const int nB = blockIdx.z, o0 = blockIdx.y * TMT, t0 = blockIdx.x * TNT;

    const uint32_t sb = smem_u32(smem_raw);

    const int m0 = (wid >> 2) * 64;
    const int nw = (wid & 3) * 32;
    const int arow = lane & 15, acb = lane >> 4;
    const int brow = (lane & 7) + ((lane >> 4) << 3), bcb = (lane >> 3) & 1;
    uint32_t aoff[4], a7[4], boff[2], b7[2];
    #pragma unroll
    for (int mf = 0; mf < 4; mf++) {
        int r = m0 + mf * 16 + arow;
        aoff[mf] = (uint32_t)(r * 128); a7[mf] = (uint32_t)(r & 7);
    }
    #pragma unroll
    for (int p = 0; p < 2; p++) {
        int r = nw + p * 16 + brow;
        boff[p] = (uint32_t)(r * 128); b7[p] = (uint32_t)(r & 7);
    }

    float acc[4][4][4];
    #pragma unroll
    for (int a = 0; a < 4; a++)
        #pragma unroll
        for (int b = 0; b < 4; b++)
            #pragma unroll
            for (int c = 0; c < 4; c++) acc[a][b][c] = 0.f;

    auto load_chunk = [&](int c, int s) {
        const int tap = c >> 3, ci0 = (c & 7) * 64;
        const __nv_bfloat16 *bh, *bl; int ro;
        if (tap == 0)      { bh = B0h; bl = B0l; ro = r0off; }
        else if (tap == 1) { bh = B1h; bl = B1l; ro = r1off; }
        else               { bh = B2h; bl = B2l; ro = r2off; }
        const size_t brow0 = (size_t)nB * TPAD + 1 + t0 + ro;
        const __nv_bfloat16* wh = Wh + ((size_t)tap * C_ + o0) * C_ + ci0;
        const __nv_bfloat16* wl = Wl + ((size_t)tap * C_ + o0) * C_ + ci0;
        const uint32_t st = sb + (uint32_t)s * (uint32_t)STAGE_BYTES;
        #pragma unroll
        for (int it = 0; it < 4; it++) {
            int i = tid + it * 256;          // 0..1023 = 128 rows x 8 chunks
            int row = i >> 3, q = i & 7;
            uint32_t so = (uint32_t)(row * 128 + ((q ^ (row & 7)) << 4));
            cp_async16(st + so,          wh + (size_t)row * C_ + q * 8);
            cp_async16(st + 16384u + so, wl + (size_t)row * C_ + q * 8);
            const size_t bo = (brow0 + row) * C_ + ci0 + q * 8;
            cp_async16(st + 32768u + so, bh + bo);
            cp_async16(st + 49152u + so, bl + bo);
        }
        asm volatile("cp.async.commit_group;" ::: "memory");
    };

    auto compute = [&](int s) {
        const uint32_t Ab  = sb + (uint32_t)s * (uint32_t)STAGE_BYTES;
        const uint32_t Alb = Ab + 16384u;
        const uint32_t Bb  = Ab + 32768u;
        const uint32_t Blb = Ab + 49152u;
        #pragma unroll
        for (int ks = 0; ks < 4; ks++) {
            uint32_t ah[4][4], al[4][4], bhv[2][4], blv[2][4];
            #pragma unroll
            for (int mf = 0; mf < 4; mf++) {
                uint32_t off = aoff[mf] + ((((uint32_t)(2*ks) + acb) ^ a7[mf]) << 4);
                ldsm4(ah[mf], Ab + off);
                ldsm4(al[mf], Alb + off);
            }
            #pragma unroll
            for (int p = 0; p < 2; p++) {
                uint32_t off = boff[p] + ((((uint32_t)(2*ks) + bcb) ^ b7[p]) << 4);
                ldsm4(bhv[p], Bb + off);
                ldsm4(blv[p], Blb + off);
            }
            #pragma unroll
            for (int mf = 0; mf < 4; mf++) {
                #pragma unroll
                for (int nf = 0; nf < 4; nf++) {
                    int p = nf >> 1, j = (nf & 1) * 2;
                    mma16816(acc[mf][nf], ah[mf], bhv[p][j], bhv[p][j+1]);
                    mma16816(acc[mf][nf], ah[mf], blv[p][j], blv[p][j+1]);
                    mma16816(acc[mf][nf], al[mf], bhv[p][j], bhv[p][j+1]);
                }
            }
        }
    };

    load_chunk(0, 0);
    load_chunk(1, 1);
    for (int c = 0; c < NCHUNK; c++) {
        if (c == NCHUNK - 1) asm volatile("cp.async.wait_group 0;" ::: "memory");
        else                 asm volatile("cp.async.wait_group 1;" ::: "memory");
        __syncthreads();
        if (c + 2 < NCHUNK) load_chunk(c + 2, (c + 2) % STAGES);
        compute(c % STAGES);
    }

    // epilogue (+ optional fused GroupNorm partial stats, deterministic)
    __shared__ float ws[8][4][2];
    #pragma unroll
    for (int mf = 0; mf < 4; mf++) {
        int rowA = o0 + m0 + mf * 16 + (lane >> 2);
        int rowB = rowA + 8;
        float bA = bias[rowA], bB = bias[rowB];
        float* pA = out + ((size_t)nB * C_ + rowA) * T_ + t0;
        float* pB = out + ((size_t)nB * C_ + rowB) * T_ + t0;
        float s = 0.f, q = 0.f;
        #pragma unroll
        for (int nf = 0; nf < 4; nf++) {
            int col = nw + nf * 8 + (lane & 3) * 2;
            float2 vA = make_float2(acc[mf][nf][0] + bA, acc[mf][nf][1] + bA);
            float2 vB = make_float2(acc[mf][nf][2] + bB, acc[mf][nf][3] + bB);
            if (stats) {
                s += vA.x + vA.y + vB.x + vB.y;
                q += vA.x*vA.x + vA.y*vA.y + vB.x*vB.x + vB.y*vB.y;
            }
            if (relu) {
                vA.x = fmaxf(vA.x, 0.f); vA.y = fmaxf(vA.y, 0.f);
                vB.x = fmaxf(vB.x, 0.f); vB.y = fmaxf(vB.y, 0.f);
            }
            *reinterpret_cast<float2*>(pA + col) = vA;
            *reinterpret_cast<float2*>(pB + col) = vB;
        }
        if (stats) {
            #pragma unroll
            for (int d = 16; d > 0; d >>= 1) {
                s += __shfl_xor_sync(0xffffffffu, s, d);
                q += __shfl_xor_sync(0xffffffffu, q, d);
            }
            if (lane == 0) { ws[wid][mf][0] = s; ws[wid][mf][1] = q; }
        }
    }
    if (stats) {
        __syncthreads();
        if (tid < 8) {
            int qd = tid >> 2, mf = tid & 3;
            float s = 0.f, q = 0.f;
            #pragma unroll
            for (int w = 0; w < 4; w++) {
                s += ws[qd * 4 + w][mf][0];
                q += ws[qd * 4 + w][mf][1];
            }
            int g = o0 / 16 + qd * 4 + mf;
            g_psum[nB][g][blockIdx.x]   = s;
            g_psumsq[nB][g][blockIdx.x] = q;
        }
    }
}

// ---------------- finalize GroupNorm stats ----------------
__global__ void gn_finalize_kernel() {
    int idx = blockIdx.x * blockDim.x + threadIdx.x;
    if (idx >= N_ * G_) return;
    int n = idx / G_, g = idx % G_;
    float s = 0.f, q = 0.f;
    #pragma unroll
    for (int b = 0; b < 32; b++) { s += g_psum[n][g][b]; q += g_psumsq[n][g][b]; }
    const float M = 16.f * T_;
    float m = s / M;
    float var = q / M - m * m;
    g_mean[idx] = m;
    g_rstd[idx] = rsqrtf(var + EPS_);
}

// ---------------- normalize+relu -> hT hi/lo planes (transposed) ----------------
__global__ __launch_bounds__(256) void norm_t_kernel(const float* __restrict__ gamma,
                                                     const float* __restrict__ beta) {
    __shared__ float st[64][65];
    int n = blockIdx.z, c0 = blockIdx.y * 64, t0 = blockIdx.x * 64;
    for (int i = threadIdx.x; i < 64 * 64; i += 256) {
        int ci = i >> 6, t = i & 63;
        int c = c0 + ci;
        float v = g_h[((size_t)n * C_ + c) * T_ + t0 + t];
        int gi = n * G_ + (c >> 4);
        v = fmaxf((v - g_mean[gi]) * g_rstd[gi] * gamma[c] + beta[c], 0.f);
        st[ci][t] = v;
    }
    __syncthreads();
    for (int i = threadIdx.x; i < 64 * 64; i += 256) {
        int ci = i & 63, t = i >> 6;
        float v = st[ci][t];
        size_t dst = ((size_t)n * TPAD + 1 + t0 + t) * C_ + c0 + ci;
        __nv_bfloat16 h = __float2bfloat16_rn(v);
        g_hTh[dst] = h;
        g_hTl[dst] = __float2bfloat16_rn(v - __bfloat162float(h));
    }
}

// ---------------- bilinear sampling -> S0/S2 hi/lo (reads hT hi/lo, vectorized) ----------------
__global__ __launch_bounds__(256) void sample_kernel(const float* __restrict__ locs,
                                                     const int* __restrict__ stride_p) {
    const int n = blockIdx.y;
    int sv = *stride_p;
    float fs = (sv > 0 && sv < 1000000) ? (float)sv : __int_as_float(sv);

    const int ci2 = threadIdx.x;   // bf162 index: channels 2*ci2, 2*ci2+1

    #pragma unroll
    for (int tt = 0; tt < 4; tt++) {
        int t = blockIdx.x * 4 + tt;
        float y1 = locs[((size_t)n * 2 + 0) * T_ + t] / fs;
        float y2 = locs[((size_t)n * 2 + 1) * T_ + t] / fs;

        float pos0 = (float)t - 1.0f - y1;
        float f0 = floorf(pos0);
        float wb0 = pos0 - f0;
        int i00 = (int)f0, i01 = i00 + 1;
        float m00 = (i00 >= 0 && i00 < T_) ? 1.f : 0.f;
        float m01 = (i01 >= 0 && i01 < T_) ? 1.f : 0.f;
        size_t r00 = ((size_t)n * TPAD + 1 + min(max(i00, 0), T_ - 1)) * C_;
        size_t r01 = ((size_t)n * TPAD + 1 + min(max(i01, 0), T_ - 1)) * C_;

        float pos2 = (float)t + 1.0f + y2;
        float f2 = floorf(pos2);
        float wb2 = pos2 - f2;
        int i20 = (int)f2, i21 = i20 + 1;
        float m20 = (i20 >= 0 && i20 < T_) ? 1.f : 0.f;
        float m21 = (i21 >= 0 && i21 < T_) ? 1.f : 0.f;
        size_t r20 = ((size_t)n * TPAD + 1 + min(max(i20, 0), T_ - 1)) * C_;
        size_t r21 = ((size_t)n * TPAD + 1 + min(max(i21, 0), T_ - 1)) * C_;

        size_t dst = ((size_t)n * TPAD + 1 + t) * C_;

        __nv_bfloat162 a0h = ((const __nv_bfloat162*)(g_hTh + r00))[ci2];
        __nv_bfloat162 a0l = ((const __nv_bfloat162*)(g_hTl + r00))[ci2];
        __nv_bfloat162 b0h = ((const __nv_bfloat162*)(g_hTh + r01))[ci2];
        __nv_bfloat162 b0l = ((const __nv_bfloat162*)(g_hTl + r01))[ci2];
        __nv_bfloat162 a2h = ((const __nv_bfloat162*)(g_hTh + r20))[ci2];
        __nv_bfloat162 a2l = ((const __nv_bfloat162*)(g_hTl + r20))[ci2];
        __nv_bfloat162 b2h = ((const __nv_bfloat162*)(g_hTh + r21))[ci2];
        __nv_bfloat162 b2l = ((const __nv_bfloat162*)(g_hTl + r21))[ci2];

        float w0a = (1.f - wb0) * m00, w0b = wb0 * m01;
        float w2a = (1.f - wb2) * m20, w2b = wb2 * m21;

        float s0x = (__bfloat162float(a0h.x) + __bfloat162float(a0l.x)) * w0a
                  + (__bfloat162float(b0h.x) + __bfloat162float(b0l.x)) * w0b;
        float s0y = (__bfloat162float(a0h.y) + __bfloat162float(a0l.y)) * w0a
                  + (__bfloat162float(b0h.y) + __bfloat162float(b0l.y)) * w0b;
        float s2x = (__bfloat162float(a2h.x) + __bfloat162float(a2l.x)) * w2a
                  + (__bfloat162float(b2h.x) + __bfloat162float(b2l.x)) * w2b;
        float s2y = (__bfloat162float(a2h.y) + __bfloat162float(a2l.y)) * w2a
                  + (__bfloat162float(b2h.y) + __bfloat162float(b2l.y)) * w2b;

        __nv_bfloat16 h0x = __float2bfloat16_rn(s0x);
        __nv_bfloat16 h0y = __float2bfloat16_rn(s0y);
        __nv_bfloat16 h2x = __float2bfloat16_rn(s2x);
        __nv_bfloat16 h2y = __float2bfloat16_rn(s2y);

        ((__nv_bfloat162*)(g_S0h + dst))[ci2] = __nv_bfloat162(h0x, h0y);
        ((__nv_bfloat162*)(g_S0l + dst))[ci2] = __nv_bfloat162(
            __float2bfloat16_rn(s0x - __bfloat162float(h0x)),
            __float2bfloat16_rn(s0y - __bfloat162float(h0y)));
        ((__nv_bfloat162*)(g_S2h + dst))[ci2] = __nv_bfloat162(h2x, h2y);
        ((__nv_bfloat162*)(g_S2l + dst))[ci2] = __nv_bfloat162(
            __float2bfloat16_rn(s2x - __bfloat162float(h2x)),
            __float2bfloat16_rn(s2y - __bfloat162float(h2y)));
    }
}

// ---------------- final 512->2 conv ----------------
__global__ __launch_bounds__(256) void outconv_kernel(const float* __restrict__ W,
                                                      const float* __restrict__ b,
                                                      const float* __restrict__ feat,
                                                      float* __restrict__ out) {
    __shared__ float sW[2 * C_ * 3];
    for (int l = threadIdx.x; l < 2 * C_ * 3; l += 256) sW[l] = W[l];
    __syncthreads();

    int idx = blockIdx.x * blockDim.x + threadIdx.x;
    int t = idx % T_;
    int n = idx / T_;
    const float* fb = feat + (size_t)n * C_ * T_;
    float a0 = b[0], a1 = b[1];
    bool lok = (t >= 1), rok = (t < T_ - 1);
    for (int i = 0; i < C_; i++) {
        const float* fr = fb + (size_t)i * T_ + t;
        float vm = lok ? fr[-1] : 0.0f;
        float v0 = fr[0];
        float vp = rok ? fr[1] : 0.0f;
        a0 = fmaf(sW[i*3+0], vm, a0);
        a0 = fmaf(sW[i*3+1], v0, a0);
        a0 = fmaf(sW[i*3+2], vp, a0);
        a1 = fmaf(sW[(C_+i)*3+0], vm, a1);
        a1 = fmaf(sW[(C_+i)*3+1], v0, a1);
        a1 = fmaf(sW[(C_+i)*3+2], vp, a1);
    }
    out[(size_t)n * 2 * T_ + t]       = a0;
    out[((size_t)n * 2 + 1) * T_ + t] = a1;
}

// ---------------------------------------------------------------------------
extern "C" void kernel_launch(void* const* d_in, const int* in_sizes, int n_in,
                              void* d_out, int out_size) {
    const float* feat   = (const float*)d_in[0];
    const float* locs   = (const float*)d_in[1];
    const float* conv_w = (const float*)d_in[2];
    const float* conv_b = (const float*)d_in[3];
    const float* gn_g   = (const float*)d_in[4];
    const float* gn_b   = (const float*)d_in[5];
    const float* dcn_w  = (const float*)d_in[6];
    const float* dcn_b  = (const float*)d_in[7];
    const float* out_w  = (const float*)d_in[8];
    const float* out_b  = (const float*)d_in[9];
    const int*   stride = (const int*)d_in[10];

    float* out      = (float*)d_out;
    float* out_feat = (float*)d_out + OFFSET_ELEMS;

    __nv_bfloat16 *w1h, *w1l, *w2h, *w2l;
    __nv_bfloat16 *xth, *xtl, *hth, *htl, *s0h, *s0l, *s2h, *s2l;
    float *hbuf;
    cudaGetSymbolAddress((void**)&w1h, g_Wh);  w2h = w1h + 3*C_*C_;
    cudaGetSymbolAddress((void**)&w1l, g_Wl);  w2l = w1l + 3*C_*C_;
    cudaGetSymbolAddress((void**)&xth, g_xTh);
    cudaGetSymbolAddress((void**)&xtl, g_xTl);
    cudaGetSymbolAddress((void**)&hth, g_hTh);
    cudaGetSymbolAddress((void**)&htl, g_hTl);
    cudaGetSymbolAddress((void**)&s0h, g_S0h);
    cudaGetSymbolAddress((void**)&s0l, g_S0l);
    cudaGetSymbolAddress((void**)&s2h, g_S2h);
    cudaGetSymbolAddress((void**)&s2l, g_S2l);
    cudaGetSymbolAddress((void**)&hbuf, g_h);

    const int SMEM_BYTES = STAGES * STAGE_BYTES;   // 192 KB
    cudaFuncSetAttribute(gemm_kernel, cudaFuncAttributeMaxDynamicSharedMemorySize, SMEM_BYTES);

    dim3 tr_grid(T_/64, C_/64, N_);
    dim3 gemm_grid(T_/TNT, C_/TMT, N_);   // (32, 4, 8)

    prep_w_kernel<<<dim3(512, 2), 256>>>(conv_w, dcn_w);
    prep_x_kernel<<<tr_grid, 256>>>(feat);
    zero_guard_kernel<<<(N_*C_ + 255)/256, 256>>>();
    gemm_kernel<<<gemm_grid, 256, SMEM_BYTES>>>(w1h, w1l,
        xth, xtl, xth, xtl, xth, xtl, -1, 0, 1, conv_b, hbuf, 0, 1);
    gn_finalize_kernel<<<1, 256>>>();
    norm_t_kernel<<<tr_grid, 256>>>(gn_g, gn_b);
    sample_kernel<<<dim3(T_/4, N_), 256>>>(locs, stride);
    gemm_kernel<<<gemm_grid, 256, SMEM_BYTES>>>(w2h, w2l,
        s0h, s0l, hth, htl, s2h, s2l, 0, 0, 0, dcn_b, out_feat, 1, 0);
    outconv_kernel<<<(N_*T_ + 255)/256, 256>>>(out_w, out_b, out_feat, out);
}